// round 16
// baseline (speedup 1.0000x reference)
#include <cuda_runtime.h>
#include <cuda_fp16.h>
#include <math.h>
#include <stdint.h>

#define BB  65536
#define DIN 128
#define HH  256
#define DE  64
#define KC  4096

// ---------------- scratch (static device globals; no allocation) ----------------
__device__ float g_h1[(size_t)BB * HH];
__device__ float g_ps[512 * HH];
__device__ float g_pq[512 * HH];
__device__ float g_ps2[16 * HH];
__device__ float g_pq2[16 * HH];
__device__ float g_scale[HH];
__device__ float g_shift[HH];
__device__ float g_c2[KC];
__device__ float g_bv[2 * BB];
__device__ int   g_bi[2 * BB];
__device__ uint32_t g_cb1[32 * 4096];
__device__ uint32_t g_cb2[32 * 4096];
__device__ uint32_t g_af1h[4096 * 8 * 128];
__device__ uint32_t g_af1l[4096 * 8 * 128];
__device__ uint32_t g_af2h[4096 * 16 * 128];
__device__ uint32_t g_af2l[4096 * 16 * 128];
__device__ uint32_t g_af3h[4096 * 16 * 128];
__device__ uint32_t g_af3l[4096 * 16 * 128];
__device__ uint32_t g_zfh[4096 * 4 * 128];
__device__ uint32_t g_zfl[4096 * 4 * 128];
__device__ uint32_t g_w1h[32 * 8 * 64];
__device__ uint32_t g_w1l[32 * 8 * 64];
__device__ uint32_t g_w2h[32 * 16 * 64];
__device__ uint32_t g_w2l[32 * 16 * 64];
__device__ uint32_t g_w3h[8 * 16 * 64];
__device__ uint32_t g_w3l[8 * 16 * 64];

__device__ __forceinline__ uint32_t smem_u32(const void* p) {
    uint32_t a;
    asm("{ .reg .u64 t; cvta.to.shared.u64 t, %1; cvt.u32.u64 %0, t; }" : "=r"(a) : "l"(p));
    return a;
}
__device__ __forceinline__ void cp16(uint32_t dst, const void* src) {
    asm volatile("cp.async.cg.shared.global [%0], [%1], 16;" :: "r"(dst), "l"(src));
}
#define CP_COMMIT() asm volatile("cp.async.commit_group;" ::: "memory")
#define CP_WAIT0()  asm volatile("cp.async.wait_group 0;" ::: "memory")

__device__ __forceinline__ uint32_t packh2(float a, float b) {
    __half2 t = __floats2half2_rn(a, b);
    return *reinterpret_cast<uint32_t*>(&t);
}
__device__ __forceinline__ void split2(float a, float b, uint32_t& h, uint32_t& l) {
    h = packh2(a, b);
    const float ra = a - __half2float(__float2half_rn(a));
    const float rb = b - __half2float(__float2half_rn(b));
    l = packh2(ra, rb);
}
__device__ __forceinline__ void mma_f16(float c[4], uint32_t a0, uint32_t a1,
                                        uint32_t a2, uint32_t a3,
                                        uint32_t b0, uint32_t b1) {
    asm volatile(
        "mma.sync.aligned.m16n8k16.row.col.f32.f16.f16.f32 "
        "{%0,%1,%2,%3}, {%4,%5,%6,%7}, {%8,%9}, {%0,%1,%2,%3};"
        : "+f"(c[0]), "+f"(c[1]), "+f"(c[2]), "+f"(c[3])
        : "r"(a0), "r"(a1), "r"(a2), "r"(a3), "r"(b0), "r"(b1));
}

// ================= A-operand -> fp16 hi/lo fragments (m16n8k16 row A) =========
template<int KST, bool BN>
__global__ void __launch_bounds__(256) cvt_a_kernel(
    const float* __restrict__ A, uint32_t* __restrict__ dh, uint32_t* __restrict__ dl)
{
    constexpr int K = KST * 16;
    constexpr int LK = (KST == 8) ? 3 : 4;
    const int gid = blockIdx.x * 256 + threadIdx.x;
    const int lane = gid & 31;
    const int ks = (gid >> 5) & (KST - 1);
    const int mtg = gid >> (5 + LK);

    const int r0 = mtg * 16 + (lane >> 2);
    const int kb = ks * 16 + 2 * (lane & 3);

    float2 v00 = *reinterpret_cast<const float2*>(A + (size_t)r0 * K + kb);
    float2 v02 = *reinterpret_cast<const float2*>(A + (size_t)r0 * K + kb + 8);
    float2 v10 = *reinterpret_cast<const float2*>(A + (size_t)(r0 + 8) * K + kb);
    float2 v12 = *reinterpret_cast<const float2*>(A + (size_t)(r0 + 8) * K + kb + 8);

    if (BN) {
        const float s0 = g_scale[kb],     t0 = g_shift[kb];
        const float s1 = g_scale[kb + 1], t1 = g_shift[kb + 1];
        const float s2 = g_scale[kb + 8], t2 = g_shift[kb + 8];
        const float s3 = g_scale[kb + 9], t3 = g_shift[kb + 9];
        v00.x = fmaxf(fmaf(v00.x, s0, t0), 0.f); v00.y = fmaxf(fmaf(v00.y, s1, t1), 0.f);
        v02.x = fmaxf(fmaf(v02.x, s2, t2), 0.f); v02.y = fmaxf(fmaf(v02.y, s3, t3), 0.f);
        v10.x = fmaxf(fmaf(v10.x, s0, t0), 0.f); v10.y = fmaxf(fmaf(v10.y, s1, t1), 0.f);
        v12.x = fmaxf(fmaf(v12.x, s2, t2), 0.f); v12.y = fmaxf(fmaf(v12.y, s3, t3), 0.f);
    }

    uint4 h, l;
    split2(v00.x, v00.y, h.x, l.x);
    split2(v10.x, v10.y, h.y, l.y);
    split2(v02.x, v02.y, h.z, l.z);
    split2(v12.x, v12.y, h.w, l.w);

    const size_t o = ((size_t)(mtg * KST + ks) * 32 + lane) * 4;
    *reinterpret_cast<uint4*>(dh + o) = h;
    *reinterpret_cast<uint4*>(dl + o) = l;
}

// ================= all weights -> fp16 hi/lo B-fragments (one launch) =========
__global__ void __launch_bounds__(256) cvt_w_all_kernel(
    const float* __restrict__ W1, const float* __restrict__ W2,
    const float* __restrict__ W3)
{
    const int b = blockIdx.x;
    const float* W;
    uint32_t *dh, *dl;
    int KST, N, b0;
    if (b < 32)      { W = W1; dh = g_w1h; dl = g_w1l; KST = 8;  N = 256; b0 = 0; }
    else if (b < 96) { W = W2; dh = g_w2h; dl = g_w2l; KST = 16; N = 256; b0 = 32; }
    else             { W = W3; dh = g_w3h; dl = g_w3l; KST = 16; N = 64;  b0 = 96; }

    const int gid = (b - b0) * 256 + threadIdx.x;
    const int lane = gid & 31;
    const int ks = (gid >> 5) % KST;
    const int ntg = gid / (32 * KST);

    const int n = ntg * 8 + (lane >> 2);
    const int k0 = ks * 16 + 2 * (lane & 3);

    uint2 h, l;
    split2(W[(size_t)k0 * N + n],       W[(size_t)(k0 + 1) * N + n], h.x, l.x);
    split2(W[(size_t)(k0 + 8) * N + n], W[(size_t)(k0 + 9) * N + n], h.y, l.y);

    const size_t o = ((size_t)(ntg * KST + ks) * 32 + lane) * 2;
    *reinterpret_cast<uint2*>(dh + o) = h;
    *reinterpret_cast<uint2*>(dl + o) = l;
}

// ========== fp16 3-term split tensor GEMM, 128x128 CTA tile, 2-kstep chunks ====
#define HG_AH(b) ((b) * 16384)
#define HG_AL(b) (HG_AH(b) + 8192)
#define HG_BH(b) (32768 + (b) * 16384)
#define HG_BL(b) (HG_BH(b) + 8192)
#define HG_RED   65536
#define HG_SMEM(bnacc) (65536 + ((bnacc) ? 16384 : 0))

template<int KST>
__device__ __forceinline__ void hg_prefetch(
    uint32_t sb, int buf, int ck,
    const uint32_t* __restrict__ Ah, const uint32_t* __restrict__ Al,
    const uint32_t* __restrict__ Bh, const uint32_t* __restrict__ Bl,
    int mtg0, int ntg0, int tid)
{
    #pragma unroll
    for (int t = 0; t < 2; t++) {
        const int bi = t * 8 + (tid >> 5);
        const int mt = bi >> 1, ksl = bi & 1;
        const size_t gsrc = ((size_t)((mtg0 + mt) * KST + ck * 2 + ksl)) * 128 + (tid & 31) * 4;
        const uint32_t doff = (uint32_t)(((mt * 2 + ksl) * 128 + (tid & 31) * 4) << 2);
        cp16(sb + HG_AH(buf) + doff, Ah + gsrc);
        cp16(sb + HG_AL(buf) + doff, Al + gsrc);
    }
    #pragma unroll
    for (int t = 0; t < 2; t++) {
        const int bi = t * 16 + (tid >> 4);
        const int nt = bi >> 1, ksl = bi & 1;
        const size_t gsrc = ((size_t)((ntg0 + nt) * KST + ck * 2 + ksl)) * 64 + (tid & 15) * 4;
        const uint32_t doff = (uint32_t)(((nt * 2 + ksl) * 64 + (tid & 15) * 4) << 2);
        cp16(sb + HG_BH(buf) + doff, Bh + gsrc);
        cp16(sb + HG_BL(buf) + doff, Bl + gsrc);
    }
    CP_COMMIT();
}

template<int KST, int EPI, bool BNACC, bool FRAGOUT>
__global__ void __launch_bounds__(256, 2) hgemm_kernel(
    const uint32_t* __restrict__ Ah, const uint32_t* __restrict__ Al,
    const uint32_t* __restrict__ Bh, const uint32_t* __restrict__ Bl,
    const float* __restrict__ bias, float* __restrict__ C,
    float* __restrict__ ps, float* __restrict__ pq,
    uint32_t* __restrict__ dh, uint32_t* __restrict__ dl)
{
    extern __shared__ char smem[];
    const uint32_t sb = smem_u32(smem);
    constexpr int NCH = KST / 2;

    const int tid  = threadIdx.x;
    const int lane = tid & 31;
    const int wid  = tid >> 5;
    const int wr   = wid >> 2;
    const int wc   = wid & 3;
    const int mtg0 = blockIdx.y * 8;
    const int ntg0 = blockIdx.x * 16;

    hg_prefetch<KST>(sb, 0, 0, Ah, Al, Bh, Bl, mtg0, ntg0, tid);

    float acc[4][4][4];
    #pragma unroll
    for (int mt = 0; mt < 4; mt++)
        #pragma unroll
        for (int nt = 0; nt < 4; nt++)
            #pragma unroll
            for (int j = 0; j < 4; j++) acc[mt][nt][j] = 0.f;

    for (int ck = 0; ck < NCH; ck++) {
        const int buf = ck & 1;
        CP_WAIT0();
        __syncthreads();   // all threads done with iter ck-1 (incl. reads of buf^1)
        if (ck + 1 < NCH)
            hg_prefetch<KST>(sb, buf ^ 1, ck + 1, Ah, Al, Bh, Bl, mtg0, ntg0, tid);

        const uint32_t* sAh = (const uint32_t*)(smem + HG_AH(buf));
        const uint32_t* sAl = (const uint32_t*)(smem + HG_AL(buf));
        const uint32_t* sBh = (const uint32_t*)(smem + HG_BH(buf));
        const uint32_t* sBl = (const uint32_t*)(smem + HG_BL(buf));

        #pragma unroll
        for (int ks = 0; ks < 2; ks++) {
            uint4 a1[4], a2[4];
            uint2 b1[4], b2[4];
            #pragma unroll
            for (int mt = 0; mt < 4; mt++) {
                const int o = (((wr * 4 + mt) * 2 + ks) * 32 + lane) * 4;
                a1[mt] = *reinterpret_cast<const uint4*>(sAh + o);
                a2[mt] = *reinterpret_cast<const uint4*>(sAl + o);
            }
            #pragma unroll
            for (int nt = 0; nt < 4; nt++) {
                const int o = (((wc * 4 + nt) * 2 + ks) * 32 + lane) * 2;
                b1[nt] = *reinterpret_cast<const uint2*>(sBh + o);
                b2[nt] = *reinterpret_cast<const uint2*>(sBl + o);
            }
            #pragma unroll
            for (int mt = 0; mt < 4; mt++)
                #pragma unroll
                for (int nt = 0; nt < 4; nt++)
                    mma_f16(acc[mt][nt], a1[mt].x, a1[mt].y, a1[mt].z, a1[mt].w,
                            b1[nt].x, b1[nt].y);
            #pragma unroll
            for (int mt = 0; mt < 4; mt++)
                #pragma unroll
                for (int nt = 0; nt < 4; nt++)
                    mma_f16(acc[mt][nt], a1[mt].x, a1[mt].y, a1[mt].z, a1[mt].w,
                            b2[nt].x, b2[nt].y);
            #pragma unroll
            for (int mt = 0; mt < 4; mt++)
                #pragma unroll
                for (int nt = 0; nt < 4; nt++)
                    mma_f16(acc[mt][nt], a2[mt].x, a2[mt].y, a2[mt].z, a2[mt].w,
                            b1[nt].x, b1[nt].y);
        }
        // no trailing sync: next iter's top barrier orders buffer reuse
    }

    // ---- bias (+ReLU) in place ----
    #pragma unroll
    for (int nt = 0; nt < 4; nt++) {
        const int c0 = blockIdx.x * 128 + wc * 32 + nt * 8 + 2 * (lane & 3);
        const float bv0 = bias[c0], bv1 = bias[c0 + 1];
        #pragma unroll
        for (int mt = 0; mt < 4; mt++) {
            acc[mt][nt][0] += bv0;
            acc[mt][nt][1] += bv1;
            acc[mt][nt][2] += bv0;
            acc[mt][nt][3] += bv1;
            if (EPI == 1) {
                acc[mt][nt][0] = fmaxf(acc[mt][nt][0], 0.f);
                acc[mt][nt][1] = fmaxf(acc[mt][nt][1], 0.f);
                acc[mt][nt][2] = fmaxf(acc[mt][nt][2], 0.f);
                acc[mt][nt][3] = fmaxf(acc[mt][nt][3], 0.f);
            }
        }
    }

    if (FRAGOUT) {
        #pragma unroll
        for (int mt = 0; mt < 4; mt++) {
            const int mtg_glob = blockIdx.y * 8 + wr * 4 + mt;
            #pragma unroll
            for (int ntp = 0; ntp < 2; ntp++) {
                const int ks_glob = blockIdx.x * 8 + wc * 2 + ntp;
                uint4 h, l;
                split2(acc[mt][2 * ntp][0],     acc[mt][2 * ntp][1],     h.x, l.x);
                split2(acc[mt][2 * ntp][2],     acc[mt][2 * ntp][3],     h.y, l.y);
                split2(acc[mt][2 * ntp + 1][0], acc[mt][2 * ntp + 1][1], h.z, l.z);
                split2(acc[mt][2 * ntp + 1][2], acc[mt][2 * ntp + 1][3], h.w, l.w);
                const size_t o = ((size_t)(mtg_glob * 16 + ks_glob) * 32 + lane) * 4;
                *reinterpret_cast<uint4*>(dh + o) = h;
                *reinterpret_cast<uint4*>(dl + o) = l;
            }
        }
    } else {
        #pragma unroll
        for (int nt = 0; nt < 4; nt++) {
            const int c0 = blockIdx.x * 128 + wc * 32 + nt * 8 + 2 * (lane & 3);
            #pragma unroll
            for (int mt = 0; mt < 4; mt++) {
                const int r = blockIdx.y * 128 + wr * 64 + mt * 16 + (lane >> 2);
                *reinterpret_cast<float2*>(C + (size_t)r * HH + c0) =
                    make_float2(acc[mt][nt][0], acc[mt][nt][1]);
                *reinterpret_cast<float2*>(C + (size_t)(r + 8) * HH + c0) =
                    make_float2(acc[mt][nt][2], acc[mt][nt][3]);
            }
        }
    }

    if (BNACC) {
        float* red = (float*)(smem + HG_RED);
        float cs[8], cq[8];
        #pragma unroll
        for (int j = 0; j < 8; j++) { cs[j] = 0.f; cq[j] = 0.f; }
        #pragma unroll
        for (int nt = 0; nt < 4; nt++)
            #pragma unroll
            for (int mt = 0; mt < 4; mt++) {
                const float v0 = acc[mt][nt][0], v1 = acc[mt][nt][1];
                const float v2 = acc[mt][nt][2], v3 = acc[mt][nt][3];
                cs[nt * 2 + 0] += v0 + v2;
                cs[nt * 2 + 1] += v1 + v3;
                cq[nt * 2 + 0] = fmaf(v0, v0, fmaf(v2, v2, cq[nt * 2 + 0]));
                cq[nt * 2 + 1] = fmaf(v1, v1, fmaf(v3, v3, cq[nt * 2 + 1]));
            }
        const int slot = wr * 8 + (lane >> 2);
        #pragma unroll
        for (int nt = 0; nt < 4; nt++) {
            #pragma unroll
            for (int h = 0; h < 2; h++) {
                const int cl = wc * 32 + nt * 8 + 2 * (lane & 3) + h;
                red[cl * 16 + slot]        = cs[nt * 2 + h];
                red[2048 + cl * 16 + slot] = cq[nt * 2 + h];
            }
        }
        __syncthreads();
        if (tid < 128) {
            float s = 0.f, q = 0.f;
            #pragma unroll
            for (int t = 0; t < 16; t++) {
                s += red[tid * 16 + t];
                q += red[2048 + tid * 16 + t];
            }
            ps[(size_t)blockIdx.y * HH + blockIdx.x * 128 + tid] = s;
            pq[(size_t)blockIdx.y * HH + blockIdx.x * 128 + tid] = q;
        }
    }
}

// ===== GEMM3: fp16 3-term, 128x64 CTA, 2-kstep chunks (48KB, 2 CTAs/SM) =======
#define H3_AH(b) ((b) * 16384)
#define H3_AL(b) (H3_AH(b) + 8192)
#define H3_BH(b) (32768 + (b) * 8192)
#define H3_BL(b) (H3_BH(b) + 4096)
#define H3_SMEM  49152

__global__ void __launch_bounds__(256, 2) hgemm3_kernel(
    const uint32_t* __restrict__ Ah, const uint32_t* __restrict__ Al,
    const float* __restrict__ bias,
    uint32_t* __restrict__ dh, uint32_t* __restrict__ dl)
{
    extern __shared__ char smem[];
    const uint32_t sb = smem_u32(smem);

    const int tid  = threadIdx.x;
    const int lane = tid & 31;
    const int wid  = tid >> 5;
    const int wr   = wid >> 2;
    const int wc   = wid & 3;
    const int mtg0 = blockIdx.x * 8;

    auto prefetch = [&](int buf, int ck) {
        #pragma unroll
        for (int t = 0; t < 2; t++) {
            const int bi = t * 8 + (tid >> 5);
            const int mt = bi >> 1, ksl = bi & 1;
            const size_t gsrc = ((size_t)((mtg0 + mt) * 16 + ck * 2 + ksl)) * 128 + (tid & 31) * 4;
            const uint32_t doff = (uint32_t)(((mt * 2 + ksl) * 128 + (tid & 31) * 4) << 2);
            cp16(sb + H3_AH(buf) + doff, Ah + gsrc);
            cp16(sb + H3_AL(buf) + doff, Al + gsrc);
        }
        {
            const int g = tid >> 4;
            const int nt = g >> 1, ksl = g & 1;
            const size_t gsrc = ((size_t)(nt * 16 + ck * 2 + ksl)) * 64 + (tid & 15) * 4;
            const uint32_t doff = (uint32_t)(((nt * 2 + ksl) * 64 + (tid & 15) * 4) << 2);
            cp16(sb + H3_BH(buf) + doff, g_w3h + gsrc);
            cp16(sb + H3_BL(buf) + doff, g_w3l + gsrc);
        }
        CP_COMMIT();
    };

    prefetch(0, 0);

    float acc[4][2][4];
    #pragma unroll
    for (int mt = 0; mt < 4; mt++)
        #pragma unroll
        for (int nt = 0; nt < 2; nt++)
            #pragma unroll
            for (int j = 0; j < 4; j++) acc[mt][nt][j] = 0.f;

    for (int ck = 0; ck < 8; ck++) {
        const int buf = ck & 1;
        CP_WAIT0();
        __syncthreads();
        if (ck + 1 < 8) prefetch(buf ^ 1, ck + 1);

        const uint32_t* sAh = (const uint32_t*)(smem + H3_AH(buf));
        const uint32_t* sAl = (const uint32_t*)(smem + H3_AL(buf));
        const uint32_t* sBh = (const uint32_t*)(smem + H3_BH(buf));
        const uint32_t* sBl = (const uint32_t*)(smem + H3_BL(buf));

        #pragma unroll
        for (int ks = 0; ks < 2; ks++) {
            uint4 a1[4], a2[4];
            uint2 b1[2], b2[2];
            #pragma unroll
            for (int mt = 0; mt < 4; mt++) {
                const int o = (((wr * 4 + mt) * 2 + ks) * 32 + lane) * 4;
                a1[mt] = *reinterpret_cast<const uint4*>(sAh + o);
                a2[mt] = *reinterpret_cast<const uint4*>(sAl + o);
            }
            #pragma unroll
            for (int nt = 0; nt < 2; nt++) {
                const int o = (((wc * 2 + nt) * 2 + ks) * 32 + lane) * 2;
                b1[nt] = *reinterpret_cast<const uint2*>(sBh + o);
                b2[nt] = *reinterpret_cast<const uint2*>(sBl + o);
            }
            #pragma unroll
            for (int mt = 0; mt < 4; mt++)
                #pragma unroll
                for (int nt = 0; nt < 2; nt++) {
                    mma_f16(acc[mt][nt], a1[mt].x, a1[mt].y, a1[mt].z, a1[mt].w,
                            b1[nt].x, b1[nt].y);
                    mma_f16(acc[mt][nt], a1[mt].x, a1[mt].y, a1[mt].z, a1[mt].w,
                            b2[nt].x, b2[nt].y);
                    mma_f16(acc[mt][nt], a2[mt].x, a2[mt].y, a2[mt].z, a2[mt].w,
                            b1[nt].x, b1[nt].y);
                }
        }
        // no trailing sync
    }

    // ---- tanh epilogue + z A-fragment output (ks_z = wc) ----
    #pragma unroll
    for (int mt = 0; mt < 4; mt++) {
        const int mtg_glob = blockIdx.x * 8 + wr * 4 + mt;
        float v[2][4];
        #pragma unroll
        for (int nt = 0; nt < 2; nt++) {
            const int c0 = wc * 16 + nt * 8 + 2 * (lane & 3);
            const float bv0 = bias[c0], bv1 = bias[c0 + 1];
            v[nt][0] = tanhf(acc[mt][nt][0] + bv0);
            v[nt][1] = tanhf(acc[mt][nt][1] + bv1);
            v[nt][2] = tanhf(acc[mt][nt][2] + bv0);
            v[nt][3] = tanhf(acc[mt][nt][3] + bv1);
        }
        uint4 h, l;
        split2(v[0][0], v[0][1], h.x, l.x);
        split2(v[0][2], v[0][3], h.y, l.y);
        split2(v[1][0], v[1][1], h.z, l.z);
        split2(v[1][2], v[1][3], h.w, l.w);
        const size_t o = ((size_t)(mtg_glob * 4 + wc) * 32 + lane) * 4;
        *reinterpret_cast<uint4*>(dh + o) = h;
        *reinterpret_cast<uint4*>(dl + o) = l;
    }
}

// ---------------- BN finalize: parallel two-stage -----------------
__global__ void bn_stage1_kernel()
{
    const int j = threadIdx.x;
    const int b0 = blockIdx.x * 32;
    float s = 0.f, q = 0.f;
    #pragma unroll 8
    for (int r = 0; r < 32; r++) {
        s += g_ps[(size_t)(b0 + r) * HH + j];
        q += g_pq[(size_t)(b0 + r) * HH + j];
    }
    g_ps2[blockIdx.x * HH + j] = s;
    g_pq2[blockIdx.x * HH + j] = q;
}

__global__ void bn_stage2_kernel(const float* __restrict__ gamma,
                                 const float* __restrict__ beta)
{
    const int j = threadIdx.x;
    float s = 0.f, q = 0.f;
    #pragma unroll
    for (int b = 0; b < 16; b++) { s += g_ps2[b * HH + j]; q += g_pq2[b * HH + j]; }
    const float mean = s * (1.f / (float)BB);
    const float var  = q * (1.f / (float)BB) - mean * mean;
    const float inv  = rsqrtf(var + 1e-5f);
    const float sc   = gamma[j] * inv;
    g_scale[j] = sc;
    g_shift[j] = beta[j] - mean * sc;
}

// ---------------- codebook squared norms: warp per code -----------
__global__ void __launch_bounds__(256) c2_kernel(const float* __restrict__ cb)
{
    const int code = (blockIdx.x * 256 + threadIdx.x) >> 5;
    const int lane = threadIdx.x & 31;
    const float2 v = *reinterpret_cast<const float2*>(cb + (size_t)code * DE + lane * 2);
    float s = fmaf(v.x, v.x, v.y * v.y);
    #pragma unroll
    for (int off = 16; off > 0; off >>= 1)
        s += __shfl_down_sync(0xffffffff, s, off);
    if (lane == 0) g_c2[code] = s;
}

// ---------------- codebook -> fp16 hi/lo B-fragments (dist, per chunk) ---------
__global__ void cvt_cb_kernel(const float* __restrict__ cb)
{
    const int ch = blockIdx.x;
    const int tid = threadIdx.x;
    const float* src = cb + (size_t)ch * 8192;
    #pragma unroll
    for (int t = 0; t < 16; t++) {
        const int lin = t * 256 + tid;
        const int n = lin >> 5, k2 = lin & 31;
        const float2 v = *reinterpret_cast<const float2*>(src + n * 64 + 2 * k2);
        uint32_t h, l;
        split2(v.x, v.y, h, l);
        const int nt = n >> 3, nn = n & 7;
        const int ks = k2 >> 3, kk2 = k2 & 7;
        const int o = ((nt * 4 + ks) * 32 + nn * 4 + (kk2 & 3)) * 2 + (kk2 >> 2);
        g_cb1[ch * 4096 + o] = h;
        g_cb2[ch * 4096 + o] = l;
    }
}

// ======= fp16 3-term dist + argmin: R10 core (2-way column split, 2 CTA/SM) =====
#define D_A1   0
#define D_A2   16384
#define D_B1(buf) (32768 + (buf) * 32768)
#define D_B2(buf) (D_B1(buf) + 16384)
#define D_C2   98304
#define D_REDF 32768        // aliases B1(0)
#define D_REDI 40960        // aliases B2(0) region (within B1(0) span)
#define D_SMEM 99328

__global__ void __launch_bounds__(256, 2) dist_argmin_mma(
    float* __restrict__ bvo, int* __restrict__ bio)
{
    extern __shared__ char smem[];
    const uint32_t sb = smem_u32(smem);
    float* c2s  = (float*)(smem + D_C2);

    const int tid  = threadIdx.x;
    const int lane = tid & 31;
    const int wid  = tid >> 5;
    const int wr   = wid >> 2;
    const int wc   = wid & 3;
    const int row0 = blockIdx.x * 128;
    const int half = blockIdx.y;
    const int ch0  = half * 16;

    {
        const uint4* zh = (const uint4*)(g_zfh + (size_t)blockIdx.x * 4096);
        const uint4* zl = (const uint4*)(g_zfl + (size_t)blockIdx.x * 4096);
        #pragma unroll
        for (int t = 0; t < 4; t++) {
            cp16(sb + D_A1 + (t * 256 + tid) * 16, zh + t * 256 + tid);
            cp16(sb + D_A2 + (t * 256 + tid) * 16, zl + t * 256 + tid);
        }
        const uint4* g1 = (const uint4*)(g_cb1 + ch0 * 4096);
        const uint4* g2 = (const uint4*)(g_cb2 + ch0 * 4096);
        #pragma unroll
        for (int t = 0; t < 4; t++) {
            cp16(sb + D_B1(0) + (t * 256 + tid) * 16, g1 + t * 256 + tid);
            cp16(sb + D_B2(0) + (t * 256 + tid) * 16, g2 + t * 256 + tid);
        }
        if (tid < 32) cp16(sb + D_C2 + tid * 16, (const uint4*)(g_c2 + ch0 * 128) + tid);
        CP_COMMIT();
    }

    const uint32_t* sA1 = (const uint32_t*)(smem + D_A1);
    const uint32_t* sA2 = (const uint32_t*)(smem + D_A2);

    float bestv[8];
    int   besti[8];
    #pragma unroll
    for (int s = 0; s < 8; s++) { bestv[s] = 3.4e38f; besti[s] = 0; }

    for (int cc = 0; cc < 16; cc++) {
        const int ch = ch0 + cc;
        const int buf = cc & 1;
        CP_WAIT0();
        __syncthreads();   // all threads done with iter cc-1 (incl. reads of buf^1)

        if (cc + 1 < 16) {
            const uint4* g1 = (const uint4*)(g_cb1 + (ch + 1) * 4096);
            const uint4* g2 = (const uint4*)(g_cb2 + (ch + 1) * 4096);
            const uint32_t b1 = sb + D_B1(buf ^ 1);
            const uint32_t b2 = sb + D_B2(buf ^ 1);
            #pragma unroll
            for (int t = 0; t < 4; t++) {
                cp16(b1 + (t * 256 + tid) * 16, g1 + t * 256 + tid);
                cp16(b2 + (t * 256 + tid) * 16, g2 + t * 256 + tid);
            }
            if (tid < 32)
                cp16(sb + D_C2 + (buf ^ 1) * 512 + tid * 16,
                     (const uint4*)(g_c2 + (ch + 1) * 128) + tid);
            CP_COMMIT();
        }

        const uint32_t* sB1 = (const uint32_t*)(smem + D_B1(buf));
        const uint32_t* sB2 = (const uint32_t*)(smem + D_B2(buf));

        float acc[4][4][4];
        #pragma unroll
        for (int mt = 0; mt < 4; mt++)
            #pragma unroll
            for (int nt = 0; nt < 4; nt++)
                #pragma unroll
                for (int j = 0; j < 4; j++) acc[mt][nt][j] = 0.f;

        #pragma unroll
        for (int ks = 0; ks < 4; ks++) {
            uint4 a1[4], a2[4];
            uint2 b1[4], b2[4];
            #pragma unroll
            for (int mt = 0; mt < 4; mt++) {
                const int o = (((wr * 4 + mt) * 4 + ks) * 32 + lane) * 4;
                a1[mt] = *reinterpret_cast<const uint4*>(sA1 + o);
                a2[mt] = *reinterpret_cast<const uint4*>(sA2 + o);
            }
            #pragma unroll
            for (int nt = 0; nt < 4; nt++) {
                const int o = (((wc * 4 + nt) * 4 + ks) * 32 + lane) * 2;
                b1[nt] = *reinterpret_cast<const uint2*>(sB1 + o);
                b2[nt] = *reinterpret_cast<const uint2*>(sB2 + o);
            }
            #pragma unroll
            for (int mt = 0; mt < 4; mt++)
                #pragma unroll
                for (int nt = 0; nt < 4; nt++)
                    mma_f16(acc[mt][nt], a1[mt].x, a1[mt].y, a1[mt].z, a1[mt].w,
                            b1[nt].x, b1[nt].y);
            #pragma unroll
            for (int mt = 0; mt < 4; mt++)
                #pragma unroll
                for (int nt = 0; nt < 4; nt++)
                    mma_f16(acc[mt][nt], a1[mt].x, a1[mt].y, a1[mt].z, a1[mt].w,
                            b2[nt].x, b2[nt].y);
            #pragma unroll
            for (int mt = 0; mt < 4; mt++)
                #pragma unroll
                for (int nt = 0; nt < 4; nt++)
                    mma_f16(acc[mt][nt], a2[mt].x, a2[mt].y, a2[mt].z, a2[mt].w,
                            b1[nt].x, b1[nt].y);
        }

        const float* c2p = c2s + buf * 128;
        #pragma unroll
        for (int nt = 0; nt < 4; nt++) {
            const int ncol = wc * 32 + nt * 8 + 2 * (lane & 3);
            const float2 cc2 = *reinterpret_cast<const float2*>(c2p + ncol);
            const int gi = ch * 128 + ncol;
            #pragma unroll
            for (int mt = 0; mt < 4; mt++) {
                const float d0 = fmaf(-2.f, acc[mt][nt][0], cc2.x);
                const float d1 = fmaf(-2.f, acc[mt][nt][1], cc2.y);
                const float d2 = fmaf(-2.f, acc[mt][nt][2], cc2.x);
                const float d3 = fmaf(-2.f, acc[mt][nt][3], cc2.y);
                const int s0 = mt * 2, s1 = mt * 2 + 1;
                if (d0 < bestv[s0]) { bestv[s0] = d0; besti[s0] = gi; }
                if (d1 < bestv[s0]) { bestv[s0] = d1; besti[s0] = gi + 1; }
                if (d2 < bestv[s1]) { bestv[s1] = d2; besti[s1] = gi; }
                if (d3 < bestv[s1]) { bestv[s1] = d3; besti[s1] = gi + 1; }
            }
        }
        // no trailing sync: next iter's top barrier orders buffer reuse
    }

    // ---- reduction (aliases B-buffer-0 smem; safe: B(0) last read at cc=14,
    //      and every thread passed cc=15's top barrier before reaching here) ----
    __syncthreads();   // all threads out of the mainloop before aliasing writes
    float* redF = (float*)(smem + D_REDF);
    int*   redI = (int*)(smem + D_REDI);
    #pragma unroll
    for (int s = 0; s < 8; s++) {
        const int mt = s >> 1, hf = s & 1;
        const int row = wr * 64 + mt * 16 + hf * 8 + (lane >> 2);
        const int e = wc * 4 + (lane & 3);
        redF[row * 16 + e] = bestv[s];
        redI[row * 16 + e] = besti[s];
    }
    __syncthreads();
    if (tid < 128) {
        float bs = 3.4e38f;
        int   b  = 0x7fffffff;
        #pragma unroll
        for (int e = 0; e < 16; e++) {
            const float sv = redF[tid * 16 + e];
            const int   iv = redI[tid * 16 + e];
            if (sv < bs || (sv == bs && iv < b)) { bs = sv; b = iv; }
        }
        bvo[half * BB + row0 + tid] = bs;
        bio[half * BB + row0 + tid] = b;
    }
}

// ---------------- output writer (merges 2 code halves) ----------------
__global__ void writeout_kernel(const float* __restrict__ cb,
                                const float* __restrict__ bv, const int* __restrict__ bi,
                                float* __restrict__ outf, int* __restrict__ outi,
                                int mode)
{
    const int gid = blockIdx.x * 256 + threadIdx.x;
    const int row = gid >> 6, j = gid & 63;
    const float v0 = bv[row], v1 = bv[BB + row];
    const int id = (v0 <= v1) ? bi[row] : bi[BB + row];   // tie -> half 0 (lower index)
    if (mode == 0) {
        if (j == 0) outf[row] = (float)id;
        outf[BB + gid] = cb[(size_t)id * DE + j];
    } else if (mode == 1) {
        outf[gid] = cb[(size_t)id * DE + j];
    } else {
        if (j == 0) outi[row] = id;
    }
}

// ---------------- launch -----------------------------------------------------------
extern "C" void kernel_launch(void* const* d_in, const int* in_sizes, int n_in,
                              void* d_out, int out_size)
{
    const float* x     = (const float*)d_in[0];
    const float* W1    = (const float*)d_in[1];
    const float* b1    = (const float*)d_in[2];
    const float* gamma = (const float*)d_in[3];
    const float* beta  = (const float*)d_in[4];
    const float* W2    = (const float*)d_in[5];
    const float* b2    = (const float*)d_in[6];
    const float* W3    = (const float*)d_in[7];
    const float* b3    = (const float*)d_in[8];
    const float* cb    = (const float*)d_in[9];

    float *h1p = nullptr, *psp = nullptr, *pqp = nullptr, *bvp = nullptr;
    int *bip = nullptr;
    uint32_t *a1h, *a1l, *a2h, *a2l, *a3h, *a3l, *zfh, *zfl;
    uint32_t *w1h, *w1l, *w2h, *w2l;
    cudaGetSymbolAddress((void**)&h1p, g_h1);
    cudaGetSymbolAddress((void**)&psp, g_ps);
    cudaGetSymbolAddress((void**)&pqp, g_pq);
    cudaGetSymbolAddress((void**)&bvp, g_bv);
    cudaGetSymbolAddress((void**)&bip, g_bi);
    cudaGetSymbolAddress((void**)&a1h, g_af1h);
    cudaGetSymbolAddress((void**)&a1l, g_af1l);
    cudaGetSymbolAddress((void**)&a2h, g_af2h);
    cudaGetSymbolAddress((void**)&a2l, g_af2l);
    cudaGetSymbolAddress((void**)&a3h, g_af3h);
    cudaGetSymbolAddress((void**)&a3l, g_af3l);
    cudaGetSymbolAddress((void**)&zfh, g_zfh);
    cudaGetSymbolAddress((void**)&zfl, g_zfl);
    cudaGetSymbolAddress((void**)&w1h, g_w1h);
    cudaGetSymbolAddress((void**)&w1l, g_w1l);
    cudaGetSymbolAddress((void**)&w2h, g_w2h);
    cudaGetSymbolAddress((void**)&w2l, g_w2l);

    cudaFuncSetAttribute(dist_argmin_mma, cudaFuncAttributeMaxDynamicSharedMemorySize, D_SMEM);
    cudaFuncSetAttribute(hgemm_kernel<8, 0, true, false>,
                         cudaFuncAttributeMaxDynamicSharedMemorySize, HG_SMEM(true));
    cudaFuncSetAttribute(hgemm_kernel<16, 1, false, true>,
                         cudaFuncAttributeMaxDynamicSharedMemorySize, HG_SMEM(false));
    cudaFuncSetAttribute(hgemm3_kernel, cudaFuncAttributeMaxDynamicSharedMemorySize, H3_SMEM);

    dim3 blk(256);

    // prep: operand conversions + codebook norms
    cvt_a_kernel<8, false><<<4096, blk>>>(x, a1h, a1l);
    cvt_w_all_kernel<<<112, blk>>>(W1, W2, W3);
    c2_kernel<<<512, blk>>>(cb);
    cvt_cb_kernel<<<32, blk>>>(cb);

    // h1 = x @ W1 + b1 (fp16 3-term, 2 CTAs/SM), fp32 out + fused BN partial sums
    hgemm_kernel<8, 0, true, false><<<dim3(2, BB / 128), blk, HG_SMEM(true)>>>(
        a1h, a1l, w1h, w1l, b1, h1p, psp, pqp, nullptr, nullptr);

    // BN finalize
    bn_stage1_kernel<<<16, HH>>>();
    bn_stage2_kernel<<<1, HH>>>(gamma, beta);

    // bnrelu(h1) -> A fragments
    cvt_a_kernel<16, true><<<8192, blk>>>(h1p, a2h, a2l);

    // h2 = relu( bnrelu(h1) @ W2 + b2 ) (fp16 3-term, 2 CTAs/SM), frag output
    hgemm_kernel<16, 1, false, true><<<dim3(2, BB / 128), blk, HG_SMEM(false)>>>(
        a2h, a2l, w2h, w2l, b2, nullptr, nullptr, nullptr, a3h, a3l);

    // z = tanh( h2 @ W3 + b3 ) (fp16 3-term, 2 CTAs/SM), output AS z A-fragments
    hgemm3_kernel<<<BB / 128, blk, H3_SMEM>>>(a3h, a3l, b3, zfh, zfl);

    // dist/argmin: R10 core, 2-way column split, 2 CTAs/SM
    dist_argmin_mma<<<dim3(BB / 128, 2), blk, D_SMEM>>>(bvp, bip);

    // outputs (merge halves)
    int mode;
    if      (out_size == BB * (DE + 1)) mode = 0;
    else if (out_size == BB * DE)       mode = 1;
    else                                mode = 2;
    writeout_kernel<<<(BB * DE) / 256, blk>>>(cb, bvp, bip, (float*)d_out, (int*)d_out, mode);
}

// round 17
// speedup vs baseline: 1.0123x; 1.0123x over previous
#include <cuda_runtime.h>
#include <cuda_fp16.h>
#include <math.h>
#include <stdint.h>

#define BB  65536
#define DIN 128
#define HH  256
#define DE  64
#define KC  4096

// ---------------- scratch (static device globals; no allocation) ----------------
__device__ float g_h1[(size_t)BB * HH];
__device__ float g_ps[512 * HH];
__device__ float g_pq[512 * HH];
__device__ float g_ps2[16 * HH];
__device__ float g_pq2[16 * HH];
__device__ float g_scale[HH];
__device__ float g_shift[HH];
__device__ float g_c2[KC];
__device__ float g_bv[2 * BB];
__device__ int   g_bi[2 * BB];
__device__ uint32_t g_cb1[32 * 4096];
__device__ uint32_t g_cb2[32 * 4096];
__device__ uint32_t g_af1h[4096 * 8 * 128];
__device__ uint32_t g_af1l[4096 * 8 * 128];
__device__ uint32_t g_af2h[4096 * 16 * 128];
__device__ uint32_t g_af2l[4096 * 16 * 128];
__device__ uint32_t g_af3h[4096 * 16 * 128];
__device__ uint32_t g_af3l[4096 * 16 * 128];
__device__ uint32_t g_zfh[4096 * 4 * 128];
__device__ uint32_t g_zfl[4096 * 4 * 128];
__device__ uint32_t g_w1h[32 * 8 * 64];
__device__ uint32_t g_w1l[32 * 8 * 64];
__device__ uint32_t g_w2h[32 * 16 * 64];
__device__ uint32_t g_w2l[32 * 16 * 64];
__device__ uint32_t g_w3h[8 * 16 * 64];
__device__ uint32_t g_w3l[8 * 16 * 64];

__device__ __forceinline__ uint32_t smem_u32(const void* p) {
    uint32_t a;
    asm("{ .reg .u64 t; cvta.to.shared.u64 t, %1; cvt.u32.u64 %0, t; }" : "=r"(a) : "l"(p));
    return a;
}
__device__ __forceinline__ void cp16(uint32_t dst, const void* src) {
    asm volatile("cp.async.cg.shared.global [%0], [%1], 16;" :: "r"(dst), "l"(src));
}
#define CP_COMMIT() asm volatile("cp.async.commit_group;" ::: "memory")
#define CP_WAIT0()  asm volatile("cp.async.wait_group 0;" ::: "memory")

__device__ __forceinline__ uint32_t packh2(float a, float b) {
    __half2 t = __floats2half2_rn(a, b);
    return *reinterpret_cast<uint32_t*>(&t);
}
__device__ __forceinline__ void split2(float a, float b, uint32_t& h, uint32_t& l) {
    h = packh2(a, b);
    const float ra = a - __half2float(__float2half_rn(a));
    const float rb = b - __half2float(__float2half_rn(b));
    l = packh2(ra, rb);
}
__device__ __forceinline__ void mma_f16(float c[4], uint32_t a0, uint32_t a1,
                                        uint32_t a2, uint32_t a3,
                                        uint32_t b0, uint32_t b1) {
    asm volatile(
        "mma.sync.aligned.m16n8k16.row.col.f32.f16.f16.f32 "
        "{%0,%1,%2,%3}, {%4,%5,%6,%7}, {%8,%9}, {%0,%1,%2,%3};"
        : "+f"(c[0]), "+f"(c[1]), "+f"(c[2]), "+f"(c[3])
        : "r"(a0), "r"(a1), "r"(a2), "r"(a3), "r"(b0), "r"(b1));
}

// ================= A-operand -> fp16 hi/lo fragments (m16n8k16 row A) =========
template<int KST, bool BN>
__global__ void __launch_bounds__(256) cvt_a_kernel(
    const float* __restrict__ A, uint32_t* __restrict__ dh, uint32_t* __restrict__ dl)
{
    constexpr int K = KST * 16;
    constexpr int LK = (KST == 8) ? 3 : 4;
    const int gid = blockIdx.x * 256 + threadIdx.x;
    const int lane = gid & 31;
    const int ks = (gid >> 5) & (KST - 1);
    const int mtg = gid >> (5 + LK);

    const int r0 = mtg * 16 + (lane >> 2);
    const int kb = ks * 16 + 2 * (lane & 3);

    float2 v00 = *reinterpret_cast<const float2*>(A + (size_t)r0 * K + kb);
    float2 v02 = *reinterpret_cast<const float2*>(A + (size_t)r0 * K + kb + 8);
    float2 v10 = *reinterpret_cast<const float2*>(A + (size_t)(r0 + 8) * K + kb);
    float2 v12 = *reinterpret_cast<const float2*>(A + (size_t)(r0 + 8) * K + kb + 8);

    if (BN) {
        const float s0 = g_scale[kb],     t0 = g_shift[kb];
        const float s1 = g_scale[kb + 1], t1 = g_shift[kb + 1];
        const float s2 = g_scale[kb + 8], t2 = g_shift[kb + 8];
        const float s3 = g_scale[kb + 9], t3 = g_shift[kb + 9];
        v00.x = fmaxf(fmaf(v00.x, s0, t0), 0.f); v00.y = fmaxf(fmaf(v00.y, s1, t1), 0.f);
        v02.x = fmaxf(fmaf(v02.x, s2, t2), 0.f); v02.y = fmaxf(fmaf(v02.y, s3, t3), 0.f);
        v10.x = fmaxf(fmaf(v10.x, s0, t0), 0.f); v10.y = fmaxf(fmaf(v10.y, s1, t1), 0.f);
        v12.x = fmaxf(fmaf(v12.x, s2, t2), 0.f); v12.y = fmaxf(fmaf(v12.y, s3, t3), 0.f);
    }

    uint4 h, l;
    split2(v00.x, v00.y, h.x, l.x);
    split2(v10.x, v10.y, h.y, l.y);
    split2(v02.x, v02.y, h.z, l.z);
    split2(v12.x, v12.y, h.w, l.w);

    const size_t o = ((size_t)(mtg * KST + ks) * 32 + lane) * 4;
    *reinterpret_cast<uint4*>(dh + o) = h;
    *reinterpret_cast<uint4*>(dl + o) = l;
}

// ====== merged prep: c2 (blocks 0..511) + cvt_w (512..623) + cvt_cb (624..751) ==
__global__ void __launch_bounds__(256) prep_kernel(
    const float* __restrict__ cb, const float* __restrict__ W1,
    const float* __restrict__ W2, const float* __restrict__ W3)
{
    const int b = blockIdx.x;
    const int tid = threadIdx.x;

    if (b < 512) {
        // ---- codebook squared norms: warp per code ----
        const int code = (b * 256 + tid) >> 5;
        const int lane = tid & 31;
        const float2 v = *reinterpret_cast<const float2*>(cb + (size_t)code * DE + lane * 2);
        float s = fmaf(v.x, v.x, v.y * v.y);
        #pragma unroll
        for (int off = 16; off > 0; off >>= 1)
            s += __shfl_down_sync(0xffffffff, s, off);
        if (lane == 0) g_c2[code] = s;
    } else if (b < 624) {
        // ---- weights -> fp16 hi/lo B-fragments ----
        const int bb = b - 512;
        const float* W;
        uint32_t *dh, *dl;
        int KST, N, b0;
        if (bb < 32)      { W = W1; dh = g_w1h; dl = g_w1l; KST = 8;  N = 256; b0 = 0; }
        else if (bb < 96) { W = W2; dh = g_w2h; dl = g_w2l; KST = 16; N = 256; b0 = 32; }
        else              { W = W3; dh = g_w3h; dl = g_w3l; KST = 16; N = 64;  b0 = 96; }

        const int gid = (bb - b0) * 256 + tid;
        const int lane = gid & 31;
        const int ks = (gid >> 5) % KST;
        const int ntg = gid / (32 * KST);

        const int n = ntg * 8 + (lane >> 2);
        const int k0 = ks * 16 + 2 * (lane & 3);

        uint2 h, l;
        split2(W[(size_t)k0 * N + n],       W[(size_t)(k0 + 1) * N + n], h.x, l.x);
        split2(W[(size_t)(k0 + 8) * N + n], W[(size_t)(k0 + 9) * N + n], h.y, l.y);

        const size_t o = ((size_t)(ntg * KST + ks) * 32 + lane) * 2;
        *reinterpret_cast<uint2*>(dh + o) = h;
        *reinterpret_cast<uint2*>(dl + o) = l;
    } else {
        // ---- codebook -> fp16 hi/lo B-fragments (dist), 4 blocks per chunk ----
        const int bb = b - 624;          // 0..127
        const int ch = bb >> 2;          // chunk 0..31
        const int q  = bb & 3;           // quarter
        const float* src = cb + (size_t)ch * 8192;
        #pragma unroll
        for (int tq = 0; tq < 4; tq++) {
            const int t = q * 4 + tq;
            const int lin = t * 256 + tid;
            const int n = lin >> 5, k2 = lin & 31;
            const float2 v = *reinterpret_cast<const float2*>(src + n * 64 + 2 * k2);
            uint32_t h, l;
            split2(v.x, v.y, h, l);
            const int nt = n >> 3, nn = n & 7;
            const int ks = k2 >> 3, kk2 = k2 & 7;
            const int o = ((nt * 4 + ks) * 32 + nn * 4 + (kk2 & 3)) * 2 + (kk2 >> 2);
            g_cb1[ch * 4096 + o] = h;
            g_cb2[ch * 4096 + o] = l;
        }
    }
}

// ========== fp16 3-term split tensor GEMM, 128x128 CTA tile, 2-kstep chunks ====
#define HG_AH(b) ((b) * 16384)
#define HG_AL(b) (HG_AH(b) + 8192)
#define HG_BH(b) (32768 + (b) * 16384)
#define HG_BL(b) (HG_BH(b) + 8192)
#define HG_RED   65536
#define HG_SMEM(bnacc) (65536 + ((bnacc) ? 16384 : 0))

template<int KST>
__device__ __forceinline__ void hg_prefetch(
    uint32_t sb, int buf, int ck,
    const uint32_t* __restrict__ Ah, const uint32_t* __restrict__ Al,
    const uint32_t* __restrict__ Bh, const uint32_t* __restrict__ Bl,
    int mtg0, int ntg0, int tid)
{
    #pragma unroll
    for (int t = 0; t < 2; t++) {
        const int bi = t * 8 + (tid >> 5);
        const int mt = bi >> 1, ksl = bi & 1;
        const size_t gsrc = ((size_t)((mtg0 + mt) * KST + ck * 2 + ksl)) * 128 + (tid & 31) * 4;
        const uint32_t doff = (uint32_t)(((mt * 2 + ksl) * 128 + (tid & 31) * 4) << 2);
        cp16(sb + HG_AH(buf) + doff, Ah + gsrc);
        cp16(sb + HG_AL(buf) + doff, Al + gsrc);
    }
    #pragma unroll
    for (int t = 0; t < 2; t++) {
        const int bi = t * 16 + (tid >> 4);
        const int nt = bi >> 1, ksl = bi & 1;
        const size_t gsrc = ((size_t)((ntg0 + nt) * KST + ck * 2 + ksl)) * 64 + (tid & 15) * 4;
        const uint32_t doff = (uint32_t)(((nt * 2 + ksl) * 64 + (tid & 15) * 4) << 2);
        cp16(sb + HG_BH(buf) + doff, Bh + gsrc);
        cp16(sb + HG_BL(buf) + doff, Bl + gsrc);
    }
    CP_COMMIT();
}

template<int KST, int EPI, bool BNACC, bool FRAGOUT>
__global__ void __launch_bounds__(256, 2) hgemm_kernel(
    const uint32_t* __restrict__ Ah, const uint32_t* __restrict__ Al,
    const uint32_t* __restrict__ Bh, const uint32_t* __restrict__ Bl,
    const float* __restrict__ bias, float* __restrict__ C,
    float* __restrict__ ps, float* __restrict__ pq,
    uint32_t* __restrict__ dh, uint32_t* __restrict__ dl)
{
    extern __shared__ char smem[];
    const uint32_t sb = smem_u32(smem);
    constexpr int NCH = KST / 2;

    const int tid  = threadIdx.x;
    const int lane = tid & 31;
    const int wid  = tid >> 5;
    const int wr   = wid >> 2;
    const int wc   = wid & 3;
    const int mtg0 = blockIdx.y * 8;
    const int ntg0 = blockIdx.x * 16;

    hg_prefetch<KST>(sb, 0, 0, Ah, Al, Bh, Bl, mtg0, ntg0, tid);

    float acc[4][4][4];
    #pragma unroll
    for (int mt = 0; mt < 4; mt++)
        #pragma unroll
        for (int nt = 0; nt < 4; nt++)
            #pragma unroll
            for (int j = 0; j < 4; j++) acc[mt][nt][j] = 0.f;

    for (int ck = 0; ck < NCH; ck++) {
        const int buf = ck & 1;
        CP_WAIT0();
        __syncthreads();
        if (ck + 1 < NCH)
            hg_prefetch<KST>(sb, buf ^ 1, ck + 1, Ah, Al, Bh, Bl, mtg0, ntg0, tid);

        const uint32_t* sAh = (const uint32_t*)(smem + HG_AH(buf));
        const uint32_t* sAl = (const uint32_t*)(smem + HG_AL(buf));
        const uint32_t* sBh = (const uint32_t*)(smem + HG_BH(buf));
        const uint32_t* sBl = (const uint32_t*)(smem + HG_BL(buf));

        #pragma unroll
        for (int ks = 0; ks < 2; ks++) {
            uint4 a1[4], a2[4];
            uint2 b1[4], b2[4];
            #pragma unroll
            for (int mt = 0; mt < 4; mt++) {
                const int o = (((wr * 4 + mt) * 2 + ks) * 32 + lane) * 4;
                a1[mt] = *reinterpret_cast<const uint4*>(sAh + o);
                a2[mt] = *reinterpret_cast<const uint4*>(sAl + o);
            }
            #pragma unroll
            for (int nt = 0; nt < 4; nt++) {
                const int o = (((wc * 4 + nt) * 2 + ks) * 32 + lane) * 2;
                b1[nt] = *reinterpret_cast<const uint2*>(sBh + o);
                b2[nt] = *reinterpret_cast<const uint2*>(sBl + o);
            }
            #pragma unroll
            for (int mt = 0; mt < 4; mt++)
                #pragma unroll
                for (int nt = 0; nt < 4; nt++)
                    mma_f16(acc[mt][nt], a1[mt].x, a1[mt].y, a1[mt].z, a1[mt].w,
                            b1[nt].x, b1[nt].y);
            #pragma unroll
            for (int mt = 0; mt < 4; mt++)
                #pragma unroll
                for (int nt = 0; nt < 4; nt++)
                    mma_f16(acc[mt][nt], a1[mt].x, a1[mt].y, a1[mt].z, a1[mt].w,
                            b2[nt].x, b2[nt].y);
            #pragma unroll
            for (int mt = 0; mt < 4; mt++)
                #pragma unroll
                for (int nt = 0; nt < 4; nt++)
                    mma_f16(acc[mt][nt], a2[mt].x, a2[mt].y, a2[mt].z, a2[mt].w,
                            b1[nt].x, b1[nt].y);
        }
    }

    // ---- bias (+ReLU) in place ----
    #pragma unroll
    for (int nt = 0; nt < 4; nt++) {
        const int c0 = blockIdx.x * 128 + wc * 32 + nt * 8 + 2 * (lane & 3);
        const float bv0 = bias[c0], bv1 = bias[c0 + 1];
        #pragma unroll
        for (int mt = 0; mt < 4; mt++) {
            acc[mt][nt][0] += bv0;
            acc[mt][nt][1] += bv1;
            acc[mt][nt][2] += bv0;
            acc[mt][nt][3] += bv1;
            if (EPI == 1) {
                acc[mt][nt][0] = fmaxf(acc[mt][nt][0], 0.f);
                acc[mt][nt][1] = fmaxf(acc[mt][nt][1], 0.f);
                acc[mt][nt][2] = fmaxf(acc[mt][nt][2], 0.f);
                acc[mt][nt][3] = fmaxf(acc[mt][nt][3], 0.f);
            }
        }
    }

    if (FRAGOUT) {
        #pragma unroll
        for (int mt = 0; mt < 4; mt++) {
            const int mtg_glob = blockIdx.y * 8 + wr * 4 + mt;
            #pragma unroll
            for (int ntp = 0; ntp < 2; ntp++) {
                const int ks_glob = blockIdx.x * 8 + wc * 2 + ntp;
                uint4 h, l;
                split2(acc[mt][2 * ntp][0],     acc[mt][2 * ntp][1],     h.x, l.x);
                split2(acc[mt][2 * ntp][2],     acc[mt][2 * ntp][3],     h.y, l.y);
                split2(acc[mt][2 * ntp + 1][0], acc[mt][2 * ntp + 1][1], h.z, l.z);
                split2(acc[mt][2 * ntp + 1][2], acc[mt][2 * ntp + 1][3], h.w, l.w);
                const size_t o = ((size_t)(mtg_glob * 16 + ks_glob) * 32 + lane) * 4;
                *reinterpret_cast<uint4*>(dh + o) = h;
                *reinterpret_cast<uint4*>(dl + o) = l;
            }
        }
    } else {
        #pragma unroll
        for (int nt = 0; nt < 4; nt++) {
            const int c0 = blockIdx.x * 128 + wc * 32 + nt * 8 + 2 * (lane & 3);
            #pragma unroll
            for (int mt = 0; mt < 4; mt++) {
                const int r = blockIdx.y * 128 + wr * 64 + mt * 16 + (lane >> 2);
                *reinterpret_cast<float2*>(C + (size_t)r * HH + c0) =
                    make_float2(acc[mt][nt][0], acc[mt][nt][1]);
                *reinterpret_cast<float2*>(C + (size_t)(r + 8) * HH + c0) =
                    make_float2(acc[mt][nt][2], acc[mt][nt][3]);
            }
        }
    }

    if (BNACC) {
        float* red = (float*)(smem + HG_RED);
        float cs[8], cq[8];
        #pragma unroll
        for (int j = 0; j < 8; j++) { cs[j] = 0.f; cq[j] = 0.f; }
        #pragma unroll
        for (int nt = 0; nt < 4; nt++)
            #pragma unroll
            for (int mt = 0; mt < 4; mt++) {
                const float v0 = acc[mt][nt][0], v1 = acc[mt][nt][1];
                const float v2 = acc[mt][nt][2], v3 = acc[mt][nt][3];
                cs[nt * 2 + 0] += v0 + v2;
                cs[nt * 2 + 1] += v1 + v3;
                cq[nt * 2 + 0] = fmaf(v0, v0, fmaf(v2, v2, cq[nt * 2 + 0]));
                cq[nt * 2 + 1] = fmaf(v1, v1, fmaf(v3, v3, cq[nt * 2 + 1]));
            }
        const int slot = wr * 8 + (lane >> 2);
        __syncthreads();
        #pragma unroll
        for (int nt = 0; nt < 4; nt++) {
            #pragma unroll
            for (int h = 0; h < 2; h++) {
                const int cl = wc * 32 + nt * 8 + 2 * (lane & 3) + h;
                red[cl * 16 + slot]        = cs[nt * 2 + h];
                red[2048 + cl * 16 + slot] = cq[nt * 2 + h];
            }
        }
        __syncthreads();
        if (tid < 128) {
            float s = 0.f, q = 0.f;
            #pragma unroll
            for (int t = 0; t < 16; t++) {
                s += red[tid * 16 + t];
                q += red[2048 + tid * 16 + t];
            }
            ps[(size_t)blockIdx.y * HH + blockIdx.x * 128 + tid] = s;
            pq[(size_t)blockIdx.y * HH + blockIdx.x * 128 + tid] = q;
        }
    }
}

// ===== GEMM3: fp16 3-term, 128x64 CTA, 2-kstep chunks (48KB, 2 CTAs/SM) =======
#define H3_AH(b) ((b) * 16384)
#define H3_AL(b) (H3_AH(b) + 8192)
#define H3_BH(b) (32768 + (b) * 8192)
#define H3_BL(b) (H3_BH(b) + 4096)
#define H3_SMEM  49152

__global__ void __launch_bounds__(256, 2) hgemm3_kernel(
    const uint32_t* __restrict__ Ah, const uint32_t* __restrict__ Al,
    const float* __restrict__ bias,
    uint32_t* __restrict__ dh, uint32_t* __restrict__ dl)
{
    extern __shared__ char smem[];
    const uint32_t sb = smem_u32(smem);

    const int tid  = threadIdx.x;
    const int lane = tid & 31;
    const int wid  = tid >> 5;
    const int wr   = wid >> 2;
    const int wc   = wid & 3;
    const int mtg0 = blockIdx.x * 8;

    auto prefetch = [&](int buf, int ck) {
        #pragma unroll
        for (int t = 0; t < 2; t++) {
            const int bi = t * 8 + (tid >> 5);
            const int mt = bi >> 1, ksl = bi & 1;
            const size_t gsrc = ((size_t)((mtg0 + mt) * 16 + ck * 2 + ksl)) * 128 + (tid & 31) * 4;
            const uint32_t doff = (uint32_t)(((mt * 2 + ksl) * 128 + (tid & 31) * 4) << 2);
            cp16(sb + H3_AH(buf) + doff, Ah + gsrc);
            cp16(sb + H3_AL(buf) + doff, Al + gsrc);
        }
        {
            const int g = tid >> 4;
            const int nt = g >> 1, ksl = g & 1;
            const size_t gsrc = ((size_t)(nt * 16 + ck * 2 + ksl)) * 64 + (tid & 15) * 4;
            const uint32_t doff = (uint32_t)(((nt * 2 + ksl) * 64 + (tid & 15) * 4) << 2);
            cp16(sb + H3_BH(buf) + doff, g_w3h + gsrc);
            cp16(sb + H3_BL(buf) + doff, g_w3l + gsrc);
        }
        CP_COMMIT();
    };

    prefetch(0, 0);

    float acc[4][2][4];
    #pragma unroll
    for (int mt = 0; mt < 4; mt++)
        #pragma unroll
        for (int nt = 0; nt < 2; nt++)
            #pragma unroll
            for (int j = 0; j < 4; j++) acc[mt][nt][j] = 0.f;

    for (int ck = 0; ck < 8; ck++) {
        const int buf = ck & 1;
        CP_WAIT0();
        __syncthreads();
        if (ck + 1 < 8) prefetch(buf ^ 1, ck + 1);

        const uint32_t* sAh = (const uint32_t*)(smem + H3_AH(buf));
        const uint32_t* sAl = (const uint32_t*)(smem + H3_AL(buf));
        const uint32_t* sBh = (const uint32_t*)(smem + H3_BH(buf));
        const uint32_t* sBl = (const uint32_t*)(smem + H3_BL(buf));

        #pragma unroll
        for (int ks = 0; ks < 2; ks++) {
            uint4 a1[4], a2[4];
            uint2 b1[2], b2[2];
            #pragma unroll
            for (int mt = 0; mt < 4; mt++) {
                const int o = (((wr * 4 + mt) * 2 + ks) * 32 + lane) * 4;
                a1[mt] = *reinterpret_cast<const uint4*>(sAh + o);
                a2[mt] = *reinterpret_cast<const uint4*>(sAl + o);
            }
            #pragma unroll
            for (int nt = 0; nt < 2; nt++) {
                const int o = (((wc * 2 + nt) * 2 + ks) * 32 + lane) * 2;
                b1[nt] = *reinterpret_cast<const uint2*>(sBh + o);
                b2[nt] = *reinterpret_cast<const uint2*>(sBl + o);
            }
            #pragma unroll
            for (int mt = 0; mt < 4; mt++)
                #pragma unroll
                for (int nt = 0; nt < 2; nt++) {
                    mma_f16(acc[mt][nt], a1[mt].x, a1[mt].y, a1[mt].z, a1[mt].w,
                            b1[nt].x, b1[nt].y);
                    mma_f16(acc[mt][nt], a1[mt].x, a1[mt].y, a1[mt].z, a1[mt].w,
                            b2[nt].x, b2[nt].y);
                    mma_f16(acc[mt][nt], a2[mt].x, a2[mt].y, a2[mt].z, a2[mt].w,
                            b1[nt].x, b1[nt].y);
                }
        }
    }

    // ---- tanh epilogue + z A-fragment output (ks_z = wc) ----
    #pragma unroll
    for (int mt = 0; mt < 4; mt++) {
        const int mtg_glob = blockIdx.x * 8 + wr * 4 + mt;
        float v[2][4];
        #pragma unroll
        for (int nt = 0; nt < 2; nt++) {
            const int c0 = wc * 16 + nt * 8 + 2 * (lane & 3);
            const float bv0 = bias[c0], bv1 = bias[c0 + 1];
            v[nt][0] = tanhf(acc[mt][nt][0] + bv0);
            v[nt][1] = tanhf(acc[mt][nt][1] + bv1);
            v[nt][2] = tanhf(acc[mt][nt][2] + bv0);
            v[nt][3] = tanhf(acc[mt][nt][3] + bv1);
        }
        uint4 h, l;
        split2(v[0][0], v[0][1], h.x, l.x);
        split2(v[0][2], v[0][3], h.y, l.y);
        split2(v[1][0], v[1][1], h.z, l.z);
        split2(v[1][2], v[1][3], h.w, l.w);
        const size_t o = ((size_t)(mtg_glob * 4 + wc) * 32 + lane) * 4;
        *reinterpret_cast<uint4*>(dh + o) = h;
        *reinterpret_cast<uint4*>(dl + o) = l;
    }
}

// ---------------- BN finalize: parallel two-stage -----------------
__global__ void bn_stage1_kernel()
{
    const int j = threadIdx.x;
    const int b0 = blockIdx.x * 32;
    float s = 0.f, q = 0.f;
    #pragma unroll 8
    for (int r = 0; r < 32; r++) {
        s += g_ps[(size_t)(b0 + r) * HH + j];
        q += g_pq[(size_t)(b0 + r) * HH + j];
    }
    g_ps2[blockIdx.x * HH + j] = s;
    g_pq2[blockIdx.x * HH + j] = q;
}

__global__ void bn_stage2_kernel(const float* __restrict__ gamma,
                                 const float* __restrict__ beta)
{
    const int j = threadIdx.x;
    float s = 0.f, q = 0.f;
    #pragma unroll
    for (int b = 0; b < 16; b++) { s += g_ps2[b * HH + j]; q += g_pq2[b * HH + j]; }
    const float mean = s * (1.f / (float)BB);
    const float var  = q * (1.f / (float)BB) - mean * mean;
    const float inv  = rsqrtf(var + 1e-5f);
    const float sc   = gamma[j] * inv;
    g_scale[j] = sc;
    g_shift[j] = beta[j] - mean * sc;
}

// ======= fp16 3-term dist + argmin: R10 core (2-way column split, 2 CTA/SM) =====
#define D_A1   0
#define D_A2   16384
#define D_B1(buf) (32768 + (buf) * 32768)
#define D_B2(buf) (D_B1(buf) + 16384)
#define D_C2   98304
#define D_REDF 32768        // aliases B1(0)
#define D_REDI 40960        // aliases B2(0) region (within B1(0) span)
#define D_SMEM 99328

__global__ void __launch_bounds__(256, 2) dist_argmin_mma(
    float* __restrict__ bvo, int* __restrict__ bio)
{
    extern __shared__ char smem[];
    const uint32_t sb = smem_u32(smem);
    float* c2s  = (float*)(smem + D_C2);

    const int tid  = threadIdx.x;
    const int lane = tid & 31;
    const int wid  = tid >> 5;
    const int wr   = wid >> 2;
    const int wc   = wid & 3;
    const int row0 = blockIdx.x * 128;
    const int half = blockIdx.y;
    const int ch0  = half * 16;

    {
        const uint4* zh = (const uint4*)(g_zfh + (size_t)blockIdx.x * 4096);
        const uint4* zl = (const uint4*)(g_zfl + (size_t)blockIdx.x * 4096);
        #pragma unroll
        for (int t = 0; t < 4; t++) {
            cp16(sb + D_A1 + (t * 256 + tid) * 16, zh + t * 256 + tid);
            cp16(sb + D_A2 + (t * 256 + tid) * 16, zl + t * 256 + tid);
        }
        const uint4* g1 = (const uint4*)(g_cb1 + ch0 * 4096);
        const uint4* g2 = (const uint4*)(g_cb2 + ch0 * 4096);
        #pragma unroll
        for (int t = 0; t < 4; t++) {
            cp16(sb + D_B1(0) + (t * 256 + tid) * 16, g1 + t * 256 + tid);
            cp16(sb + D_B2(0) + (t * 256 + tid) * 16, g2 + t * 256 + tid);
        }
        if (tid < 32) cp16(sb + D_C2 + tid * 16, (const uint4*)(g_c2 + ch0 * 128) + tid);
        CP_COMMIT();
    }

    const uint32_t* sA1 = (const uint32_t*)(smem + D_A1);
    const uint32_t* sA2 = (const uint32_t*)(smem + D_A2);

    float bestv[8];
    int   besti[8];
    #pragma unroll
    for (int s = 0; s < 8; s++) { bestv[s] = 3.4e38f; besti[s] = 0; }

    for (int cc = 0; cc < 16; cc++) {
        const int ch = ch0 + cc;
        const int buf = cc & 1;
        CP_WAIT0();
        __syncthreads();

        if (cc + 1 < 16) {
            const uint4* g1 = (const uint4*)(g_cb1 + (ch + 1) * 4096);
            const uint4* g2 = (const uint4*)(g_cb2 + (ch + 1) * 4096);
            const uint32_t b1 = sb + D_B1(buf ^ 1);
            const uint32_t b2 = sb + D_B2(buf ^ 1);
            #pragma unroll
            for (int t = 0; t < 4; t++) {
                cp16(b1 + (t * 256 + tid) * 16, g1 + t * 256 + tid);
                cp16(b2 + (t * 256 + tid) * 16, g2 + t * 256 + tid);
            }
            if (tid < 32)
                cp16(sb + D_C2 + (buf ^ 1) * 512 + tid * 16,
                     (const uint4*)(g_c2 + (ch + 1) * 128) + tid);
            CP_COMMIT();
        }

        const uint32_t* sB1 = (const uint32_t*)(smem + D_B1(buf));
        const uint32_t* sB2 = (const uint32_t*)(smem + D_B2(buf));

        float acc[4][4][4];
        #pragma unroll
        for (int mt = 0; mt < 4; mt++)
            #pragma unroll
            for (int nt = 0; nt < 4; nt++)
                #pragma unroll
                for (int j = 0; j < 4; j++) acc[mt][nt][j] = 0.f;

        #pragma unroll
        for (int ks = 0; ks < 4; ks++) {
            uint4 a1[4], a2[4];
            uint2 b1[4], b2[4];
            #pragma unroll
            for (int mt = 0; mt < 4; mt++) {
                const int o = (((wr * 4 + mt) * 4 + ks) * 32 + lane) * 4;
                a1[mt] = *reinterpret_cast<const uint4*>(sA1 + o);
                a2[mt] = *reinterpret_cast<const uint4*>(sA2 + o);
            }
            #pragma unroll
            for (int nt = 0; nt < 4; nt++) {
                const int o = (((wc * 4 + nt) * 4 + ks) * 32 + lane) * 2;
                b1[nt] = *reinterpret_cast<const uint2*>(sB1 + o);
                b2[nt] = *reinterpret_cast<const uint2*>(sB2 + o);
            }
            #pragma unroll
            for (int mt = 0; mt < 4; mt++)
                #pragma unroll
                for (int nt = 0; nt < 4; nt++)
                    mma_f16(acc[mt][nt], a1[mt].x, a1[mt].y, a1[mt].z, a1[mt].w,
                            b1[nt].x, b1[nt].y);
            #pragma unroll
            for (int mt = 0; mt < 4; mt++)
                #pragma unroll
                for (int nt = 0; nt < 4; nt++)
                    mma_f16(acc[mt][nt], a1[mt].x, a1[mt].y, a1[mt].z, a1[mt].w,
                            b2[nt].x, b2[nt].y);
            #pragma unroll
            for (int mt = 0; mt < 4; mt++)
                #pragma unroll
                for (int nt = 0; nt < 4; nt++)
                    mma_f16(acc[mt][nt], a2[mt].x, a2[mt].y, a2[mt].z, a2[mt].w,
                            b1[nt].x, b1[nt].y);
        }

        const float* c2p = c2s + buf * 128;
        #pragma unroll
        for (int nt = 0; nt < 4; nt++) {
            const int ncol = wc * 32 + nt * 8 + 2 * (lane & 3);
            const float2 cc2 = *reinterpret_cast<const float2*>(c2p + ncol);
            const int gi = ch * 128 + ncol;
            #pragma unroll
            for (int mt = 0; mt < 4; mt++) {
                const float d0 = fmaf(-2.f, acc[mt][nt][0], cc2.x);
                const float d1 = fmaf(-2.f, acc[mt][nt][1], cc2.y);
                const float d2 = fmaf(-2.f, acc[mt][nt][2], cc2.x);
                const float d3 = fmaf(-2.f, acc[mt][nt][3], cc2.y);
                const int s0 = mt * 2, s1 = mt * 2 + 1;
                if (d0 < bestv[s0]) { bestv[s0] = d0; besti[s0] = gi; }
                if (d1 < bestv[s0]) { bestv[s0] = d1; besti[s0] = gi + 1; }
                if (d2 < bestv[s1]) { bestv[s1] = d2; besti[s1] = gi; }
                if (d3 < bestv[s1]) { bestv[s1] = d3; besti[s1] = gi + 1; }
            }
        }
    }

    // ---- reduction (aliases dead B-buffer smem) ----
    __syncthreads();
    float* redF = (float*)(smem + D_REDF);
    int*   redI = (int*)(smem + D_REDI);
    #pragma unroll
    for (int s = 0; s < 8; s++) {
        const int mt = s >> 1, hf = s & 1;
        const int row = wr * 64 + mt * 16 + hf * 8 + (lane >> 2);
        const int e = wc * 4 + (lane & 3);
        redF[row * 16 + e] = bestv[s];
        redI[row * 16 + e] = besti[s];
    }
    __syncthreads();
    if (tid < 128) {
        float bs = 3.4e38f;
        int   b  = 0x7fffffff;
        #pragma unroll
        for (int e = 0; e < 16; e++) {
            const float sv = redF[tid * 16 + e];
            const int   iv = redI[tid * 16 + e];
            if (sv < bs || (sv == bs && iv < b)) { bs = sv; b = iv; }
        }
        bvo[half * BB + row0 + tid] = bs;
        bio[half * BB + row0 + tid] = b;
    }
}

// ---------------- output writer (merges 2 code halves) ----------------
__global__ void writeout_kernel(const float* __restrict__ cb,
                                const float* __restrict__ bv, const int* __restrict__ bi,
                                float* __restrict__ outf, int* __restrict__ outi,
                                int mode)
{
    const int gid = blockIdx.x * 256 + threadIdx.x;
    const int row = gid >> 6, j = gid & 63;
    const float v0 = bv[row], v1 = bv[BB + row];
    const int id = (v0 <= v1) ? bi[row] : bi[BB + row];   // tie -> half 0 (lower index)
    if (mode == 0) {
        if (j == 0) outf[row] = (float)id;
        outf[BB + gid] = cb[(size_t)id * DE + j];
    } else if (mode == 1) {
        outf[gid] = cb[(size_t)id * DE + j];
    } else {
        if (j == 0) outi[row] = id;
    }
}

// ---------------- launch -----------------------------------------------------------
extern "C" void kernel_launch(void* const* d_in, const int* in_sizes, int n_in,
                              void* d_out, int out_size)
{
    const float* x     = (const float*)d_in[0];
    const float* W1    = (const float*)d_in[1];
    const float* b1    = (const float*)d_in[2];
    const float* gamma = (const float*)d_in[3];
    const float* beta  = (const float*)d_in[4];
    const float* W2    = (const float*)d_in[5];
    const float* b2    = (const float*)d_in[6];
    const float* W3    = (const float*)d_in[7];
    const float* b3    = (const float*)d_in[8];
    const float* cb    = (const float*)d_in[9];

    float *h1p = nullptr, *psp = nullptr, *pqp = nullptr, *bvp = nullptr;
    int *bip = nullptr;
    uint32_t *a1h, *a1l, *a2h, *a2l, *a3h, *a3l, *zfh, *zfl;
    uint32_t *w1h, *w1l, *w2h, *w2l;
    cudaGetSymbolAddress((void**)&h1p, g_h1);
    cudaGetSymbolAddress((void**)&psp, g_ps);
    cudaGetSymbolAddress((void**)&pqp, g_pq);
    cudaGetSymbolAddress((void**)&bvp, g_bv);
    cudaGetSymbolAddress((void**)&bip, g_bi);
    cudaGetSymbolAddress((void**)&a1h, g_af1h);
    cudaGetSymbolAddress((void**)&a1l, g_af1l);
    cudaGetSymbolAddress((void**)&a2h, g_af2h);
    cudaGetSymbolAddress((void**)&a2l, g_af2l);
    cudaGetSymbolAddress((void**)&a3h, g_af3h);
    cudaGetSymbolAddress((void**)&a3l, g_af3l);
    cudaGetSymbolAddress((void**)&zfh, g_zfh);
    cudaGetSymbolAddress((void**)&zfl, g_zfl);
    cudaGetSymbolAddress((void**)&w1h, g_w1h);
    cudaGetSymbolAddress((void**)&w1l, g_w1l);
    cudaGetSymbolAddress((void**)&w2h, g_w2h);
    cudaGetSymbolAddress((void**)&w2l, g_w2l);

    cudaFuncSetAttribute(dist_argmin_mma, cudaFuncAttributeMaxDynamicSharedMemorySize, D_SMEM);
    cudaFuncSetAttribute(hgemm_kernel<8, 0, true, false>,
                         cudaFuncAttributeMaxDynamicSharedMemorySize, HG_SMEM(true));
    cudaFuncSetAttribute(hgemm_kernel<16, 1, false, true>,
                         cudaFuncAttributeMaxDynamicSharedMemorySize, HG_SMEM(false));
    cudaFuncSetAttribute(hgemm3_kernel, cudaFuncAttributeMaxDynamicSharedMemorySize, H3_SMEM);

    dim3 blk(256);

    // prep: x fragments + merged (c2 | weight fragments | codebook fragments)
    cvt_a_kernel<8, false><<<4096, blk>>>(x, a1h, a1l);
    prep_kernel<<<752, blk>>>(cb, W1, W2, W3);

    // h1 = x @ W1 + b1 (fp16 3-term, 2 CTAs/SM), fp32 out + fused BN partial sums
    hgemm_kernel<8, 0, true, false><<<dim3(2, BB / 128), blk, HG_SMEM(true)>>>(
        a1h, a1l, w1h, w1l, b1, h1p, psp, pqp, nullptr, nullptr);

    // BN finalize
    bn_stage1_kernel<<<16, HH>>>();
    bn_stage2_kernel<<<1, HH>>>(gamma, beta);

    // bnrelu(h1) -> A fragments
    cvt_a_kernel<16, true><<<8192, blk>>>(h1p, a2h, a2l);

    // h2 = relu( bnrelu(h1) @ W2 + b2 ) (fp16 3-term, 2 CTAs/SM), frag output
    hgemm_kernel<16, 1, false, true><<<dim3(2, BB / 128), blk, HG_SMEM(false)>>>(
        a2h, a2l, w2h, w2l, b2, nullptr, nullptr, nullptr, a3h, a3l);

    // z = tanh( h2 @ W3 + b3 ) (fp16 3-term, 2 CTAs/SM), output AS z A-fragments
    hgemm3_kernel<<<BB / 128, blk, H3_SMEM>>>(a3h, a3l, b3, zfh, zfl);

    // dist/argmin: R10 core, 2-way column split, 2 CTAs/SM
    dist_argmin_mma<<<dim3(BB / 128, 2), blk, D_SMEM>>>(bvp, bip);

    // outputs (merge halves)
    int mode;
    if      (out_size == BB * (DE + 1)) mode = 0;
    else if (out_size == BB * DE)       mode = 1;
    else                                mode = 2;
    writeout_kernel<<<(BB * DE) / 256, blk>>>(cb, bvp, bip, (float*)d_out, (int*)d_out, mode);
}